// round 11
// baseline (speedup 1.0000x reference)
#include <cuda_runtime.h>
#include <mma.h>

using namespace nvcuda;

// Problem constants (fixed by the reference)
#define B_  2
#define S_  2048
#define D_  1024
#define H_  16
#define DH_ 64
#define M_  (B_ * S_)   // 4096

// Scratch (allocation-free rule: __device__ globals)
__device__ float g_q[B_ * H_ * S_ * DH_];   // [b][h][s][dh]
__device__ float g_k[B_ * H_ * S_ * DH_];
__device__ float g_v[B_ * H_ * S_ * DH_];
__device__ float g_ctx[B_ * S_ * D_];       // [b][s][h*DH+e]

// Error-compensated tf32 split: x = hi + lo with hi = tf32(x),
// lo = tf32(x - hi). (x - hi) is exact in fp32; dropped lo*lo' term ~2^-22.
template <class Frag>
__device__ __forceinline__ void split_tf32(const Frag& f, Frag& hi, Frag& lo) {
#pragma unroll
    for (int t = 0; t < f.num_elements; t++) {
        float v = f.x[t];
        float h = wmma::__float_to_tf32(v);
        hi.x[t] = h;
        lo.x[t] = wmma::__float_to_tf32(v - h);
    }
}

// acc += a * b with both operands split (3 products)
#define MMA3(acc, aHi, aLo, bHi, bLo)            \
    do {                                         \
        wmma::mma_sync(acc, aHi, bHi, acc);      \
        wmma::mma_sync(acc, aHi, bLo, acc);      \
        wmma::mma_sync(acc, aLo, bHi, acc);      \
    } while (0)

// SMEM strides: ≡ 4 (mod 8) floats so float4 column walks are conflict-free.
#define AS_LD 44    // GEMM A tile [128][44]
#define BS_LD 132   // GEMM B tile [32][132]
#define CS_LD 132   // GEMM C epilogue tile [128][132]
#define AT_LD 68    // attention tiles

#define ASZ (128 * AS_LD)   // 5632 floats per A stage
#define BSZ (32 * BS_LD)    // 4224 floats per B stage

// ---------------------------------------------------------------------------
// Kernel 1: fused per-head QKV projection, two heads per block (3xTF32 wmma),
// double-buffered SMEM stages with register prefetch (1 barrier per k0-iter).
// grid = (M/128, H/2, 3), block = 256 (8 warps).
// Tile: BM=128, BN=128, BK=32. Warp w: rows (w>>1)*32 (2 tiles), cols
// (w&1)*64 (4 tiles). Dynamic SMEM = 78848 B: As[2][128][44]+Bs[2][32][132];
// re-used (after post-loop sync) as Cs[128][132] for the bias epilogue.
// ---------------------------------------------------------------------------
__global__ __launch_bounds__(256) void qkv_kernel(
    const float* __restrict__ x,
    const float* __restrict__ Wq, const float* __restrict__ Wk,
    const float* __restrict__ Wv,
    const float* __restrict__ bq, const float* __restrict__ bk,
    const float* __restrict__ bv)
{
    extern __shared__ float smp[];
    float* Asb = smp;                  // 2 stages of A
    float* Bsb = smp + 2 * ASZ;        // 2 stages of B
    float* Cs  = smp;                  // alias (used after post-loop sync)

    const int h0  = blockIdx.y * 2;
    const int m0  = blockIdx.x * 128;
    const int sel = blockIdx.z;

    const float* W    = (sel == 0) ? Wq : (sel == 1) ? Wk : Wv;
    const float* bias = (sel == 0) ? bq : (sel == 1) ? bk : bv;
    float*       out  = (sel == 0) ? g_q : (sel == 1) ? g_k : g_v;

    const int tid = threadIdx.x;
    const int w   = tid >> 5;
    const int wr  = w >> 1;          // 0..3 -> rows wr*32
    const int wc  = w & 1;           // 0..1 -> cols wc*64

    wmma::fragment<wmma::accumulator, 16, 16, 8, float> acc[2][4];
#pragma unroll
    for (int i = 0; i < 2; i++)
#pragma unroll
        for (int j = 0; j < 4; j++) wmma::fill_fragment(acc[i][j], 0.0f);

    auto load_tiles = [&](int k0, float4 a[4], float4 bb[4]) {
#pragma unroll
        for (int l = 0; l < 4; l++) {
            int idx = l * 256 + tid;
            int row = idx >> 3;
            int kc  = (idx & 7) * 4;
            a[l] = *(const float4*)(x + (long)(m0 + row) * D_ + k0 + kc);
        }
#pragma unroll
        for (int l = 0; l < 4; l++) {
            int idx = l * 256 + tid;
            int kr  = idx >> 5;
            int n4  = (idx & 31) * 4;
            int hoff = n4 >> 6;
            int col  = n4 & 63;
            bb[l] = *(const float4*)(W + (long)(h0 + hoff) * D_ * DH_
                                       + (long)(k0 + kr) * DH_ + col);
        }
    };
    auto store_stage = [&](int st, const float4 a[4], const float4 bb[4]) {
        float* As = Asb + st * ASZ;
        float* Bs = Bsb + st * BSZ;
#pragma unroll
        for (int l = 0; l < 4; l++) {
            int idx = l * 256 + tid;
            int row = idx >> 3;
            int kc  = (idx & 7) * 4;
            *(float4*)&As[row * AS_LD + kc] = a[l];
        }
#pragma unroll
        for (int l = 0; l < 4; l++) {
            int idx = l * 256 + tid;
            int kr  = idx >> 5;
            int n4  = (idx & 31) * 4;
            *(float4*)&Bs[kr * BS_LD + n4] = bb[l];
        }
    };

    {   // prologue: fill stage 0
        float4 a[4], bb[4];
        load_tiles(0, a, bb);
        store_stage(0, a, bb);
    }
    __syncthreads();

    int cur = 0;
    for (int k0 = 0; k0 < D_; k0 += 32) {
        const bool has_next = (k0 + 32 < D_);
        float4 a[4], bb[4];
        if (has_next) load_tiles(k0 + 32, a, bb);

        const float* As = Asb + cur * ASZ;
        const float* Bs = Bsb + cur * BSZ;
#pragma unroll
        for (int k8 = 0; k8 < 4; k8++) {
            wmma::fragment<wmma::matrix_a, 16, 16, 8, wmma::precision::tf32,
                           wmma::row_major> aF, aHi[2], aLo[2];
#pragma unroll
            for (int i = 0; i < 2; i++) {
                wmma::load_matrix_sync(aF, &As[(wr * 32 + i * 16) * AS_LD + k8 * 8], AS_LD);
                split_tf32(aF, aHi[i], aLo[i]);
            }
#pragma unroll
            for (int j = 0; j < 4; j++) {
                wmma::fragment<wmma::matrix_b, 16, 16, 8, wmma::precision::tf32,
                               wmma::row_major> bF, bHi, bLo;
                wmma::load_matrix_sync(bF, &Bs[(k8 * 8) * BS_LD + wc * 64 + j * 16], BS_LD);
                split_tf32(bF, bHi, bLo);
#pragma unroll
                for (int i = 0; i < 2; i++)
                    MMA3(acc[i][j], aHi[i], aLo[i], bHi, bLo);
            }
        }

        if (has_next) {
            store_stage(cur ^ 1, a, bb);
            __syncthreads();
            cur ^= 1;
        }
    }
    __syncthreads();   // all warps done reading As/Bs before Cs alias is written

    // Epilogue: park accumulators in SMEM, add bias, scatter per-head.
#pragma unroll
    for (int i = 0; i < 2; i++)
#pragma unroll
        for (int j = 0; j < 4; j++)
            wmma::store_matrix_sync(&Cs[(wr * 32 + i * 16) * CS_LD + wc * 64 + j * 16],
                                    acc[i][j], CS_LD, wmma::mem_row_major);
    __syncthreads();

    const int tx = tid & 15;
    const int ty = tid >> 4;
    const int j0   = tx * 8;
    const int hoff = j0 >> 6;
    const int dh0  = j0 & 63;
    const int h    = h0 + hoff;

    float bia[8];
    *(float4*)&bia[0] = *(const float4*)(bias + h * DH_ + dh0);
    *(float4*)&bia[4] = *(const float4*)(bias + h * DH_ + dh0 + 4);

#pragma unroll
    for (int r = 0; r < 8; r++) {
        int m = m0 + ty * 8 + r;
        int b = m >> 11;
        int s = m & 2047;
        const float* src = &Cs[(ty * 8 + r) * CS_LD + tx * 8];
        float* dst = out + ((long)(b * H_ + h) * S_ + s) * DH_ + dh0;
        float4 v0 = *(const float4*)src;
        float4 v1 = *(const float4*)(src + 4);
        v0.x += bia[0]; v0.y += bia[1]; v0.z += bia[2]; v0.w += bia[3];
        v1.x += bia[4]; v1.y += bia[5]; v1.z += bia[6]; v1.w += bia[7];
        *(float4*)dst       = v0;
        *(float4*)(dst + 4) = v1;
    }
}

// ---------------------------------------------------------------------------
// Kernel 2: flash attention (non-causal, exact online softmax), 3xTF32 wmma,
// with next-tile K/V register prefetch spanning the whole iteration.
// grid = (S/128, H, B), block = 256 (8 warps).
// Tile: 128 q-rows x 64 k-cols per iteration. S and O live in SMEM.
// Warp w: rows (w>>1)*32, cols (w&1)*32; both mma phases k8-outermost.
// Dynamic SMEM = 139264 B (floats, stride 68):
//   Qs[128][68] Q row-major, pre-scaled 1/8
//   Ks[64][68]  K rows j, cols dh  (matrix_b col_major for S = Q @ K^T)
//   Vs[64][68]  V rows j, cols e   (matrix_b row_major for PV)
//   Ps[128][68] S tile, then P tile
//   Os[128][68] fp32 O accumulator (rescaled by alpha in softmax phase)
// Iteration: prefetch-LDG / S / sync / softmax / sync / PV / sync /
//            store-prefetch / sync.  Prefetch loads are in flight across all
//            three compute phases; stores land only after sync(4) retires
//            every read of Ks/Vs.
// ---------------------------------------------------------------------------
__global__ __launch_bounds__(256) void attn_kernel()
{
    extern __shared__ float smp[];
    float* Qs = smp;                      // 128*68 = 8704
    float* Ks = Qs + 128 * AT_LD;         // 64*68  = 4352
    float* Vs = Ks + 64 * AT_LD;          // 4352
    float* Ps = Vs + 64 * AT_LD;          // 8704
    float* Os = Ps + 128 * AT_LD;         // 8704   total 34816 fl = 139264 B

    const int qb = blockIdx.x;
    const int h  = blockIdx.y;
    const int b  = blockIdx.z;

    const long base = (long)(b * H_ + h) * S_ * DH_;
    const float* Q = g_q + base;
    const float* K = g_k + base;
    const float* V = g_v + base;

    const int tid = threadIdx.x;
    const int w   = tid >> 5;
    const int wr  = w >> 1;          // 0..3 -> rows wr*32
    const int wc  = w & 1;           // 0..1 -> cols wc*32

    // Load Q (row-major, scaled by 1/sqrt(64) = 0.125): 2048 float4, 8/thread
#pragma unroll
    for (int l = 0; l < 8; l++) {
        int idx = l * 256 + tid;
        int row = idx >> 4;
        int kc  = (idx & 15) * 4;
        float4 a = *(const float4*)(Q + (long)(qb * 128 + row) * DH_ + kc);
        a.x *= 0.125f; a.y *= 0.125f; a.z *= 0.125f; a.w *= 0.125f;
        *(float4*)&Qs[row * AT_LD + kc] = a;
    }
    // Prologue: tile 0 of K/V straight into SMEM
#pragma unroll
    for (int l = 0; l < 4; l++) {
        int idx = l * 256 + tid;
        int row = idx >> 4;
        int kc  = (idx & 15) * 4;
        *(float4*)&Ks[row * AT_LD + kc] = *(const float4*)(K + (long)row * DH_ + kc);
        *(float4*)&Vs[row * AT_LD + kc] = *(const float4*)(V + (long)row * DH_ + kc);
    }

    // Per-row softmax state (tid < 128 owns row tid)
    float mrow = -1e30f, lden = 0.0f;

    __syncthreads();   // Qs/Ks/Vs visible before first S phase

    for (int kb = 0; kb < S_; kb += 64) {
        const bool has_next = (kb + 64 < S_);

        // ---- issue next tile's LDGs now; they retire during compute ----
        float4 kp[4], vp[4];
        if (has_next) {
#pragma unroll
            for (int l = 0; l < 4; l++) {
                int idx = l * 256 + tid;
                int row = idx >> 4;
                int kc  = (idx & 15) * 4;
                kp[l] = *(const float4*)(K + (long)(kb + 64 + row) * DH_ + kc);
                vp[l] = *(const float4*)(V + (long)(kb + 64 + row) * DH_ + kc);
            }
        }

        // ---- S = Q @ K^T : warp region 32x32, k8 outermost ----
        // Ks[j][dh] viewed as col-major B[dh][j] with ldm 68.
        {
            wmma::fragment<wmma::accumulator, 16, 16, 8, float> c[2][2];
#pragma unroll
            for (int i = 0; i < 2; i++)
#pragma unroll
                for (int jt = 0; jt < 2; jt++) wmma::fill_fragment(c[i][jt], 0.0f);

#pragma unroll
            for (int k8 = 0; k8 < 8; k8++) {
                wmma::fragment<wmma::matrix_a, 16, 16, 8, wmma::precision::tf32,
                               wmma::row_major> aF, aHi[2], aLo[2];
#pragma unroll
                for (int i = 0; i < 2; i++) {
                    wmma::load_matrix_sync(aF,
                        &Qs[(wr * 32 + i * 16) * AT_LD + k8 * 8], AT_LD);
                    split_tf32(aF, aHi[i], aLo[i]);
                }
#pragma unroll
                for (int jt = 0; jt < 2; jt++) {
                    wmma::fragment<wmma::matrix_b, 16, 16, 8, wmma::precision::tf32,
                                   wmma::col_major> bF, bHi, bLo;
                    wmma::load_matrix_sync(bF,
                        &Ks[(wc * 32 + jt * 16) * AT_LD + k8 * 8], AT_LD);
                    split_tf32(bF, bHi, bLo);
#pragma unroll
                    for (int i = 0; i < 2; i++)
                        MMA3(c[i][jt], aHi[i], aLo[i], bHi, bLo);
                }
            }
#pragma unroll
            for (int i = 0; i < 2; i++)
#pragma unroll
                for (int jt = 0; jt < 2; jt++)
                    wmma::store_matrix_sync(
                        &Ps[(wr * 32 + i * 16) * AT_LD + wc * 32 + jt * 16],
                        c[i][jt], AT_LD, wmma::mem_row_major);
        }
        __syncthreads();   // (2) S tile complete

        // ---- online softmax: one thread per row ----
        if (tid < 128) {
            float* prow = &Ps[tid * AT_LD];
            float s[64];
#pragma unroll
            for (int c = 0; c < 16; c++)
                *(float4*)&s[c * 4] = *(const float4*)&prow[c * 4];

            float mloc = s[0];
#pragma unroll
            for (int c = 1; c < 64; c++) mloc = fmaxf(mloc, s[c]);
            float mnew  = fmaxf(mrow, mloc);
            float alpha = __expf(mrow - mnew);
            mrow = mnew;

            float rs = 0.0f;
#pragma unroll
            for (int c = 0; c < 64; c++) {
                s[c] = __expf(s[c] - mnew);
                rs += s[c];
            }
            lden = lden * alpha + rs;

#pragma unroll
            for (int c = 0; c < 16; c++)
                *(float4*)&prow[c * 4] = *(const float4*)&s[c * 4];

            float* orow = &Os[tid * AT_LD];
            if (kb == 0) {
                float4 z = make_float4(0.f, 0.f, 0.f, 0.f);
#pragma unroll
                for (int c = 0; c < 16; c++) *(float4*)&orow[c * 4] = z;
            } else {
#pragma unroll
                for (int c = 0; c < 16; c++) {
                    float4 o = *(const float4*)&orow[c * 4];
                    o.x *= alpha; o.y *= alpha; o.z *= alpha; o.w *= alpha;
                    *(float4*)&orow[c * 4] = o;
                }
            }
        }
        __syncthreads();   // (3) P ready, O rescaled/zeroed

        // ---- O += P @ V : warp region rows wr*32, e-cols wc*32, k8 outer ----
        {
            wmma::fragment<wmma::accumulator, 16, 16, 8, float> c[2][2];
#pragma unroll
            for (int i = 0; i < 2; i++)
#pragma unroll
                for (int et = 0; et < 2; et++)
                    wmma::load_matrix_sync(c[i][et],
                        &Os[(wr * 32 + i * 16) * AT_LD + wc * 32 + et * 16],
                        AT_LD, wmma::mem_row_major);

#pragma unroll
            for (int k8 = 0; k8 < 8; k8++) {
                wmma::fragment<wmma::matrix_a, 16, 16, 8, wmma::precision::tf32,
                               wmma::row_major> pF, pHi[2], pLo[2];
#pragma unroll
                for (int i = 0; i < 2; i++) {
                    wmma::load_matrix_sync(pF,
                        &Ps[(wr * 32 + i * 16) * AT_LD + k8 * 8], AT_LD);
                    split_tf32(pF, pHi[i], pLo[i]);
                }
#pragma unroll
                for (int et = 0; et < 2; et++) {
                    wmma::fragment<wmma::matrix_b, 16, 16, 8, wmma::precision::tf32,
                                   wmma::row_major> bF, bHi, bLo;
                    wmma::load_matrix_sync(bF,
                        &Vs[(k8 * 8) * AT_LD + wc * 32 + et * 16], AT_LD);
                    split_tf32(bF, bHi, bLo);
#pragma unroll
                    for (int i = 0; i < 2; i++)
                        MMA3(c[i][et], pHi[i], pLo[i], bHi, bLo);
                }
            }
#pragma unroll
            for (int i = 0; i < 2; i++)
#pragma unroll
                for (int et = 0; et < 2; et++)
                    wmma::store_matrix_sync(
                        &Os[(wr * 32 + i * 16) * AT_LD + wc * 32 + et * 16],
                        c[i][et], AT_LD, wmma::mem_row_major);
        }
        __syncthreads();   // (4) every read of Ks/Vs/Ps retired

        // ---- land the prefetched tile and make it visible ----
        if (has_next) {
#pragma unroll
            for (int l = 0; l < 4; l++) {
                int idx = l * 256 + tid;
                int row = idx >> 4;
                int kc  = (idx & 15) * 4;
                *(float4*)&Ks[row * AT_LD + kc] = kp[l];
                *(float4*)&Vs[row * AT_LD + kc] = vp[l];
            }
            __syncthreads();   // (1) new K/V visible for next S phase
        }
    }

    // ---- epilogue: normalize rows, write ctx [b][s][h*DH+e] ----
    if (tid < 128) {
        float inv = 1.0f / lden;
        const float* orow = &Os[tid * AT_LD];
        float* dst = g_ctx + ((long)b * S_ + qb * 128 + tid) * D_ + h * DH_;
#pragma unroll
        for (int c = 0; c < 16; c++) {
            float4 o = *(const float4*)&orow[c * 4];
            o.x *= inv; o.y *= inv; o.z *= inv; o.w *= inv;
            *(float4*)&dst[c * 4] = o;
        }
    }
}

// ---------------------------------------------------------------------------
// Kernel 3: output projection  out = ctx @ Wo + bo  (3xTF32 wmma),
// double-buffered SMEM stages with register prefetch.
// grid = (M/128, D/128), block = 256. Same scheme as kernel 1.
// ---------------------------------------------------------------------------
__global__ __launch_bounds__(256) void oproj_kernel(
    const float* __restrict__ Wo, const float* __restrict__ bo,
    float* __restrict__ out)
{
    extern __shared__ float smp[];
    float* Asb = smp;
    float* Bsb = smp + 2 * ASZ;
    float* Cs  = smp;

    const int m0 = blockIdx.x * 128;
    const int n0 = blockIdx.y * 128;

    const int tid = threadIdx.x;
    const int w   = tid >> 5;
    const int wr  = w >> 1;
    const int wc  = w & 1;

    wmma::fragment<wmma::accumulator, 16, 16, 8, float> acc[2][4];
#pragma unroll
    for (int i = 0; i < 2; i++)
#pragma unroll
        for (int j = 0; j < 4; j++) wmma::fill_fragment(acc[i][j], 0.0f);

    auto load_tiles = [&](int k0, float4 a[4], float4 bb[4]) {
#pragma unroll
        for (int l = 0; l < 4; l++) {
            int idx = l * 256 + tid;
            int row = idx >> 3;
            int kc  = (idx & 7) * 4;
            a[l] = *(const float4*)(g_ctx + (long)(m0 + row) * D_ + k0 + kc);
        }
#pragma unroll
        for (int l = 0; l < 4; l++) {
            int idx = l * 256 + tid;
            int kr  = idx >> 5;
            int n4  = (idx & 31) * 4;
            bb[l] = *(const float4*)(Wo + (long)(k0 + kr) * D_ + n0 + n4);
        }
    };
    auto store_stage = [&](int st, const float4 a[4], const float4 bb[4]) {
        float* As = Asb + st * ASZ;
        float* Bs = Bsb + st * BSZ;
#pragma unroll
        for (int l = 0; l < 4; l++) {
            int idx = l * 256 + tid;
            int row = idx >> 3;
            int kc  = (idx & 7) * 4;
            *(float4*)&As[row * AS_LD + kc] = a[l];
        }
#pragma unroll
        for (int l = 0; l < 4; l++) {
            int idx = l * 256 + tid;
            int kr  = idx >> 5;
            int n4  = (idx & 31) * 4;
            *(float4*)&Bs[kr * BS_LD + n4] = bb[l];
        }
    };

    {
        float4 a[4], bb[4];
        load_tiles(0, a, bb);
        store_stage(0, a, bb);
    }
    __syncthreads();

    int cur = 0;
    for (int k0 = 0; k0 < D_; k0 += 32) {
        const bool has_next = (k0 + 32 < D_);
        float4 a[4], bb[4];
        if (has_next) load_tiles(k0 + 32, a, bb);

        const float* As = Asb + cur * ASZ;
        const float* Bs = Bsb + cur * BSZ;
#pragma unroll
        for (int k8 = 0; k8 < 4; k8++) {
            wmma::fragment<wmma::matrix_a, 16, 16, 8, wmma::precision::tf32,
                           wmma::row_major> aF, aHi[2], aLo[2];
#pragma unroll
            for (int i = 0; i < 2; i++) {
                wmma::load_matrix_sync(aF, &As[(wr * 32 + i * 16) * AS_LD + k8 * 8], AS_LD);
                split_tf32(aF, aHi[i], aLo[i]);
            }
#pragma unroll
            for (int j = 0; j < 4; j++) {
                wmma::fragment<wmma::matrix_b, 16, 16, 8, wmma::precision::tf32,
                               wmma::row_major> bF, bHi, bLo;
                wmma::load_matrix_sync(bF, &Bs[(k8 * 8) * BS_LD + wc * 64 + j * 16], BS_LD);
                split_tf32(bF, bHi, bLo);
#pragma unroll
                for (int i = 0; i < 2; i++)
                    MMA3(acc[i][j], aHi[i], aLo[i], bHi, bLo);
            }
        }

        if (has_next) {
            store_stage(cur ^ 1, a, bb);
            __syncthreads();
            cur ^= 1;
        }
    }
    __syncthreads();   // all warps done reading As/Bs before Cs alias is written

#pragma unroll
    for (int i = 0; i < 2; i++)
#pragma unroll
        for (int j = 0; j < 4; j++)
            wmma::store_matrix_sync(&Cs[(wr * 32 + i * 16) * CS_LD + wc * 64 + j * 16],
                                    acc[i][j], CS_LD, wmma::mem_row_major);
    __syncthreads();

    const int tx = tid & 15;
    const int ty = tid >> 4;

    float bia[8];
    *(float4*)&bia[0] = *(const float4*)(bo + n0 + tx * 8);
    *(float4*)&bia[4] = *(const float4*)(bo + n0 + tx * 8 + 4);

#pragma unroll
    for (int r = 0; r < 8; r++) {
        int mrow = m0 + ty * 8 + r;
        const float* src = &Cs[(ty * 8 + r) * CS_LD + tx * 8];
        float* dst = out + (long)mrow * D_ + n0 + tx * 8;
        float4 v0 = *(const float4*)src;
        float4 v1 = *(const float4*)(src + 4);
        v0.x += bia[0]; v0.y += bia[1]; v0.z += bia[2]; v0.w += bia[3];
        v1.x += bia[4]; v1.y += bia[5]; v1.z += bia[6]; v1.w += bia[7];
        *(float4*)dst       = v0;
        *(float4*)(dst + 4) = v1;
    }
}

// ---------------------------------------------------------------------------
// Entry point. Inputs per metadata order:
// x, Wq, Wk, Wv, bq, bk, bv, Wo, bo  (all float32). Output: [B,S,D] float32.
// Graph-capturable: kernel launches only. cudaFuncSetAttribute is a non-stream
// API (executes immediately, idempotent) — not an allocation.
// ---------------------------------------------------------------------------
extern "C" void kernel_launch(void* const* d_in, const int* in_sizes, int n_in,
                              void* d_out, int out_size)
{
    (void)in_sizes; (void)n_in; (void)out_size;

    const float* x  = (const float*)d_in[0];
    const float* Wq = (const float*)d_in[1];
    const float* Wk = (const float*)d_in[2];
    const float* Wv = (const float*)d_in[3];
    const float* bq = (const float*)d_in[4];
    const float* bk = (const float*)d_in[5];
    const float* bv = (const float*)d_in[6];
    const float* Wo = (const float*)d_in[7];
    const float* bo = (const float*)d_in[8];
    float* out = (float*)d_out;

    const int GEMM_SMEM = (2 * ASZ + 2 * BSZ) * 4;   // 78848 B
    const int ATTN_SMEM = (128*AT_LD + 64*AT_LD + 64*AT_LD + 128*AT_LD + 128*AT_LD) * 4; // 139264 B

    cudaFuncSetAttribute(qkv_kernel,
                         cudaFuncAttributeMaxDynamicSharedMemorySize, GEMM_SMEM);
    cudaFuncSetAttribute(attn_kernel,
                         cudaFuncAttributeMaxDynamicSharedMemorySize, ATTN_SMEM);
    cudaFuncSetAttribute(oproj_kernel,
                         cudaFuncAttributeMaxDynamicSharedMemorySize, GEMM_SMEM);

    qkv_kernel<<<dim3(M_ / 128, H_ / 2, 3), 256, GEMM_SMEM>>>(x, Wq, Wk, Wv, bq, bk, bv);
    attn_kernel<<<dim3(S_ / 128, H_, B_), 256, ATTN_SMEM>>>();
    oproj_kernel<<<dim3(M_ / 128, D_ / 128), 256, GEMM_SMEM>>>(Wo, bo, out);
}

// round 13
// speedup vs baseline: 2.4738x; 2.4738x over previous
#include <cuda_runtime.h>
#include <cuda_bf16.h>
#include <mma.h>

using namespace nvcuda;

// Problem constants (fixed by the reference)
#define B_  2
#define S_  2048
#define D_  1024
#define H_  16
#define DH_ 64
#define M_  (B_ * S_)   // 4096

typedef __nv_bfloat16 bf16;

// Scratch (allocation-free rule: __device__ globals)
__device__ float g_q[B_ * H_ * S_ * DH_];   // [b][h][s][dh]
__device__ float g_k[B_ * H_ * S_ * DH_];
__device__ float g_v[B_ * H_ * S_ * DH_];
__device__ float g_ctx[B_ * S_ * D_];       // [b][s][h*DH+e]

// Split one float4 into bf16 hi + bf16 lo quads (packed 8B each).
// hi = bf16(v); lo = bf16(v - hi). v - hi is exact in fp32 (residual needs
// <= 16 mantissa bits). Effective precision ~17 bits per operand; the
// dropped lo*lo' term is ~2^-34.
__device__ __forceinline__ void split4(const float4 v, uint2& h, uint2& l) {
    bf16 hh[4], ll[4];
    float vv[4] = {v.x, v.y, v.z, v.w};
#pragma unroll
    for (int i = 0; i < 4; i++) {
        hh[i] = __float2bfloat16(vv[i]);
        ll[i] = __float2bfloat16(vv[i] - __bfloat162float(hh[i]));
    }
    h = *(uint2*)hh;
    l = *(uint2*)ll;
}

// acc += a * b with both operands hi/lo split (3 products; lo*lo dropped)
#define MMA3(acc, aHi, aLo, bHi, bLo)            \
    do {                                         \
        wmma::mma_sync(acc, aHi, bHi, acc);      \
        wmma::mma_sync(acc, aHi, bLo, acc);      \
        wmma::mma_sync(acc, aLo, bHi, acc);      \
    } while (0)

// bf16 SMEM strides (elements): padded +8 halves (16B) against bank conflicts.
#define AS_LD 40    // GEMM A tile [128][40]  (32 data + 8 pad)
#define BS_LD 136   // GEMM B tile [32][136]  (128 data + 8 pad)
#define CS_LD 132   // GEMM fp32 epilogue tile [128][132]
#define AT_LD 72    // attention bf16 tiles (64 data + 8 pad)
#define SF_LD 68    // attention fp32 tiles (S scores / O accum)

#define A2 (128 * AS_LD)   // halves per A matrix
#define B2 (32 * BS_LD)    // halves per B matrix

typedef wmma::fragment<wmma::matrix_a, 16, 16, 16, bf16, wmma::row_major> FragA;
typedef wmma::fragment<wmma::matrix_b, 16, 16, 16, bf16, wmma::row_major> FragB;
typedef wmma::fragment<wmma::matrix_b, 16, 16, 16, bf16, wmma::col_major> FragBT;
typedef wmma::fragment<wmma::accumulator, 16, 16, 16, float> FragC;

// ---------------------------------------------------------------------------
// Kernel 1: fused per-head QKV projection, two heads per block (3xBF16 wmma).
// grid = (M/128, H/2, 3), block = 256 (8 warps), 2 CTAs/SM via launch_bounds.
// Tile: BM=128, BN=128, BK=32; warp w: rows (w>>1)*32, cols (w&1)*64.
// Loader converts fp32 -> bf16 hi/lo SMEM tiles ONCE per element; the mma
// loop just loads fragments (no per-fragment cvt chains).
// Dynamic SMEM = 67584 B (Cs epilogue alias dominates; bf16 tiles = 37888 B).
// ---------------------------------------------------------------------------
__global__ __launch_bounds__(256, 2) void qkv_kernel(
    const float* __restrict__ x,
    const float* __restrict__ Wq, const float* __restrict__ Wk,
    const float* __restrict__ Wv,
    const float* __restrict__ bq, const float* __restrict__ bk,
    const float* __restrict__ bv)
{
    extern __shared__ float smp[];
    bf16* Ah = (bf16*)smp;          // [128][AS_LD]
    bf16* Al = Ah + A2;
    bf16* Bh = Al + A2;             // [32][BS_LD]
    bf16* Bl = Bh + B2;
    float* Cs = smp;                // fp32 alias, used after final sync

    const int h0  = blockIdx.y * 2;
    const int m0  = blockIdx.x * 128;
    const int sel = blockIdx.z;

    const float* W    = (sel == 0) ? Wq : (sel == 1) ? Wk : Wv;
    const float* bias = (sel == 0) ? bq : (sel == 1) ? bk : bv;
    float*       out  = (sel == 0) ? g_q : (sel == 1) ? g_k : g_v;

    const int tid = threadIdx.x;
    const int w   = tid >> 5;
    const int wr  = w >> 1;          // 0..3 -> rows wr*32
    const int wc  = w & 1;           // 0..1 -> cols wc*64

    FragC acc[2][4];
#pragma unroll
    for (int i = 0; i < 2; i++)
#pragma unroll
        for (int j = 0; j < 4; j++) wmma::fill_fragment(acc[i][j], 0.0f);

    for (int k0 = 0; k0 < D_; k0 += 32) {
        // A tile 128x32: 1024 float4, 4/thread; convert+store hi/lo
#pragma unroll
        for (int l = 0; l < 4; l++) {
            int idx = l * 256 + tid;
            int row = idx >> 3;
            int kc  = (idx & 7) * 4;
            float4 a = *(const float4*)(x + (long)(m0 + row) * D_ + k0 + kc);
            uint2 h, lo;
            split4(a, h, lo);
            *(uint2*)&Ah[row * AS_LD + kc] = h;
            *(uint2*)&Al[row * AS_LD + kc] = lo;
        }
        // B tile 32x128 (two heads): 1024 float4, 4/thread
#pragma unroll
        for (int l = 0; l < 4; l++) {
            int idx = l * 256 + tid;
            int kr  = idx >> 5;
            int n4  = (idx & 31) * 4;
            int hoff = n4 >> 6;
            int col  = n4 & 63;
            float4 b = *(const float4*)(W + (long)(h0 + hoff) * D_ * DH_
                                          + (long)(k0 + kr) * DH_ + col);
            uint2 h, lo;
            split4(b, h, lo);
            *(uint2*)&Bh[kr * BS_LD + n4] = h;
            *(uint2*)&Bl[kr * BS_LD + n4] = lo;
        }
        __syncthreads();

#pragma unroll
        for (int k16 = 0; k16 < 2; k16++) {
            FragA aHi[2], aLo[2];
#pragma unroll
            for (int i = 0; i < 2; i++) {
                wmma::load_matrix_sync(aHi[i], &Ah[(wr * 32 + i * 16) * AS_LD + k16 * 16], AS_LD);
                wmma::load_matrix_sync(aLo[i], &Al[(wr * 32 + i * 16) * AS_LD + k16 * 16], AS_LD);
            }
#pragma unroll
            for (int j = 0; j < 4; j++) {
                FragB bHi, bLo;
                wmma::load_matrix_sync(bHi, &Bh[(k16 * 16) * BS_LD + wc * 64 + j * 16], BS_LD);
                wmma::load_matrix_sync(bLo, &Bl[(k16 * 16) * BS_LD + wc * 64 + j * 16], BS_LD);
#pragma unroll
                for (int i = 0; i < 2; i++)
                    MMA3(acc[i][j], aHi[i], aLo[i], bHi, bLo);
            }
        }
        __syncthreads();
    }

    // Epilogue: park accumulators in fp32 SMEM alias, add bias, scatter per-head.
#pragma unroll
    for (int i = 0; i < 2; i++)
#pragma unroll
        for (int j = 0; j < 4; j++)
            wmma::store_matrix_sync(&Cs[(wr * 32 + i * 16) * CS_LD + wc * 64 + j * 16],
                                    acc[i][j], CS_LD, wmma::mem_row_major);
    __syncthreads();

    const int tx = tid & 15;
    const int ty = tid >> 4;
    const int j0   = tx * 8;
    const int hoff = j0 >> 6;
    const int dh0  = j0 & 63;
    const int h    = h0 + hoff;

    float bia[8];
    *(float4*)&bia[0] = *(const float4*)(bias + h * DH_ + dh0);
    *(float4*)&bia[4] = *(const float4*)(bias + h * DH_ + dh0 + 4);

#pragma unroll
    for (int r = 0; r < 8; r++) {
        int m = m0 + ty * 8 + r;
        int b = m >> 11;
        int s = m & 2047;
        const float* src = &Cs[(ty * 8 + r) * CS_LD + tx * 8];
        float* dst = out + ((long)(b * H_ + h) * S_ + s) * DH_ + dh0;
        float4 v0 = *(const float4*)src;
        float4 v1 = *(const float4*)(src + 4);
        v0.x += bia[0]; v0.y += bia[1]; v0.z += bia[2]; v0.w += bia[3];
        v1.x += bia[4]; v1.y += bia[5]; v1.z += bia[6]; v1.w += bia[7];
        *(float4*)dst       = v0;
        *(float4*)(dst + 4) = v1;
    }
}

// ---------------------------------------------------------------------------
// Kernel 2: flash attention (non-causal, exact online softmax), 3xBF16 wmma.
// grid = (S/128, H, B), block = 256 (8 warps).
// Tile: 128 q-rows x 64 k-cols per iteration. Warp w: rows (w>>1)*32,
// cols (w&1)*32. All matmul operands are bf16 hi/lo SMEM tiles; S scores and
// the O accumulator are fp32 SMEM.
// Softmax: TWO threads per row (row = tid>>1, half = tid&1, 32 cols each);
// pair lanes are in-warp adjacent, so row max/sum combine is one shfl_xor(1).
// Both pair threads then compute identical mnew/alpha/lden updates.
// Dynamic SMEM = 180224 B:
//   Sf[128][68] fp32 scores        (34816 B)
//   Os[128][68] fp32 O accumulator (34816 B)
//   Qh/Ql[128][72], Kh/Kl[64][72], Vh/Vl[64][72], Ph/Pl[128][72]  (110592 B)
// K/V next tile is register-prefetched across the whole iteration.
// ---------------------------------------------------------------------------
__global__ __launch_bounds__(256) void attn_kernel()
{
    extern __shared__ float smp[];
    float* Sf = smp;                       // 128*68 fl
    float* Os = Sf + 128 * SF_LD;          // 128*68 fl
    bf16* Qh = (bf16*)(Os + 128 * SF_LD);  // [128][72]
    bf16* Ql = Qh + 128 * AT_LD;
    bf16* Kh = Ql + 128 * AT_LD;           // [64][72]
    bf16* Kl = Kh + 64 * AT_LD;
    bf16* Vh = Kl + 64 * AT_LD;            // [64][72]
    bf16* Vl = Vh + 64 * AT_LD;
    bf16* Ph = Vl + 64 * AT_LD;            // [128][72]
    bf16* Pl = Ph + 128 * AT_LD;

    const int qb = blockIdx.x;
    const int h  = blockIdx.y;
    const int b  = blockIdx.z;

    const long base = (long)(b * H_ + h) * S_ * DH_;
    const float* Q = g_q + base;
    const float* K = g_k + base;
    const float* V = g_v + base;

    const int tid = threadIdx.x;
    const int w   = tid >> 5;
    const int wr  = w >> 1;          // 0..3 -> rows wr*32
    const int wc  = w & 1;           // 0..1 -> cols wc*32

    const int srow_id = tid >> 1;    // softmax row (0..127)
    const int shalf   = tid & 1;     // which 32-col half of the row

    // Q tile (scaled 1/sqrt(64)=0.125) -> bf16 hi/lo: 2048 float4, 8/thread
#pragma unroll
    for (int l = 0; l < 8; l++) {
        int idx = l * 256 + tid;
        int row = idx >> 4;
        int kc  = (idx & 15) * 4;
        float4 a = *(const float4*)(Q + (long)(qb * 128 + row) * DH_ + kc);
        a.x *= 0.125f; a.y *= 0.125f; a.z *= 0.125f; a.w *= 0.125f;
        uint2 hh, ll;
        split4(a, hh, ll);
        *(uint2*)&Qh[row * AT_LD + kc] = hh;
        *(uint2*)&Ql[row * AT_LD + kc] = ll;
    }
    // Prologue: K/V tile 0 -> bf16 hi/lo
#pragma unroll
    for (int l = 0; l < 4; l++) {
        int idx = l * 256 + tid;
        int row = idx >> 4;
        int kc  = (idx & 15) * 4;
        uint2 hh, ll;
        split4(*(const float4*)(K + (long)row * DH_ + kc), hh, ll);
        *(uint2*)&Kh[row * AT_LD + kc] = hh;
        *(uint2*)&Kl[row * AT_LD + kc] = ll;
        split4(*(const float4*)(V + (long)row * DH_ + kc), hh, ll);
        *(uint2*)&Vh[row * AT_LD + kc] = hh;
        *(uint2*)&Vl[row * AT_LD + kc] = ll;
    }

    float mrow = -1e30f, lden = 0.0f;   // per-row softmax state (pair-replicated)

    __syncthreads();   // Q/K/V tiles visible

    for (int kb = 0; kb < S_; kb += 64) {
        const bool has_next = (kb + 64 < S_);

        // Issue next tile's LDGs now; they retire during the three phases.
        float4 kp[4], vp[4];
        if (has_next) {
#pragma unroll
            for (int l = 0; l < 4; l++) {
                int idx = l * 256 + tid;
                int row = idx >> 4;
                int kc  = (idx & 15) * 4;
                kp[l] = *(const float4*)(K + (long)(kb + 64 + row) * DH_ + kc);
                vp[l] = *(const float4*)(V + (long)(kb + 64 + row) * DH_ + kc);
            }
        }

        // ---- S = Q @ K^T : warp region 32x32, k16 outermost ----
        {
            FragC c[2][2];
#pragma unroll
            for (int i = 0; i < 2; i++)
#pragma unroll
                for (int jt = 0; jt < 2; jt++) wmma::fill_fragment(c[i][jt], 0.0f);

#pragma unroll
            for (int k16 = 0; k16 < 4; k16++) {
                FragA aHi[2], aLo[2];
#pragma unroll
                for (int i = 0; i < 2; i++) {
                    wmma::load_matrix_sync(aHi[i], &Qh[(wr * 32 + i * 16) * AT_LD + k16 * 16], AT_LD);
                    wmma::load_matrix_sync(aLo[i], &Ql[(wr * 32 + i * 16) * AT_LD + k16 * 16], AT_LD);
                }
#pragma unroll
                for (int jt = 0; jt < 2; jt++) {
                    FragBT bHi, bLo;   // Kh[j][dh] viewed col-major: B[dh][j]
                    wmma::load_matrix_sync(bHi, &Kh[(wc * 32 + jt * 16) * AT_LD + k16 * 16], AT_LD);
                    wmma::load_matrix_sync(bLo, &Kl[(wc * 32 + jt * 16) * AT_LD + k16 * 16], AT_LD);
#pragma unroll
                    for (int i = 0; i < 2; i++)
                        MMA3(c[i][jt], aHi[i], aLo[i], bHi, bLo);
                }
            }
#pragma unroll
            for (int i = 0; i < 2; i++)
#pragma unroll
                for (int jt = 0; jt < 2; jt++)
                    wmma::store_matrix_sync(
                        &Sf[(wr * 32 + i * 16) * SF_LD + wc * 32 + jt * 16],
                        c[i][jt], SF_LD, wmma::mem_row_major);
        }
        __syncthreads();   // (2) S tile complete

        // ---- online softmax: two threads per row (32 cols each) ----
        {
            const float* srow = &Sf[srow_id * SF_LD + shalf * 32];

            float mloc = -1e30f;
#pragma unroll
            for (int c4 = 0; c4 < 8; c4++) {
                float4 s = *(const float4*)&srow[c4 * 4];
                mloc = fmaxf(mloc, fmaxf(fmaxf(s.x, s.y), fmaxf(s.z, s.w)));
            }
            // combine with pair lane (same row, other half)
            mloc = fmaxf(mloc, __shfl_xor_sync(0xffffffffu, mloc, 1));
            float mnew  = fmaxf(mrow, mloc);
            float alpha = __expf(mrow - mnew);
            mrow = mnew;

            float rs = 0.0f;
#pragma unroll
            for (int c4 = 0; c4 < 8; c4++) {
                float4 s = *(const float4*)&srow[c4 * 4];
                float4 p;
                p.x = __expf(s.x - mnew);
                p.y = __expf(s.y - mnew);
                p.z = __expf(s.z - mnew);
                p.w = __expf(s.w - mnew);
                rs += (p.x + p.y) + (p.z + p.w);
                uint2 hh, ll;
                split4(p, hh, ll);
                *(uint2*)&Ph[srow_id * AT_LD + shalf * 32 + c4 * 4] = hh;
                *(uint2*)&Pl[srow_id * AT_LD + shalf * 32 + c4 * 4] = ll;
            }
            rs += __shfl_xor_sync(0xffffffffu, rs, 1);   // full-row sum, both lanes
            lden = lden * alpha + rs;

            float* orow = &Os[srow_id * SF_LD + shalf * 32];
            if (kb == 0) {
                float4 z = make_float4(0.f, 0.f, 0.f, 0.f);
#pragma unroll
                for (int c4 = 0; c4 < 8; c4++) *(float4*)&orow[c4 * 4] = z;
            } else {
#pragma unroll
                for (int c4 = 0; c4 < 8; c4++) {
                    float4 o = *(const float4*)&orow[c4 * 4];
                    o.x *= alpha; o.y *= alpha; o.z *= alpha; o.w *= alpha;
                    *(float4*)&orow[c4 * 4] = o;
                }
            }
        }
        __syncthreads();   // (3) P ready, O rescaled/zeroed

        // ---- O += P @ V : warp region rows wr*32, e-cols wc*32 ----
        {
            FragC c[2][2];
#pragma unroll
            for (int i = 0; i < 2; i++)
#pragma unroll
                for (int et = 0; et < 2; et++)
                    wmma::load_matrix_sync(c[i][et],
                        &Os[(wr * 32 + i * 16) * SF_LD + wc * 32 + et * 16],
                        SF_LD, wmma::mem_row_major);

#pragma unroll
            for (int k16 = 0; k16 < 4; k16++) {
                FragA pHi[2], pLo[2];
#pragma unroll
                for (int i = 0; i < 2; i++) {
                    wmma::load_matrix_sync(pHi[i], &Ph[(wr * 32 + i * 16) * AT_LD + k16 * 16], AT_LD);
                    wmma::load_matrix_sync(pLo[i], &Pl[(wr * 32 + i * 16) * AT_LD + k16 * 16], AT_LD);
                }
#pragma unroll
                for (int et = 0; et < 2; et++) {
                    FragB bHi, bLo;
                    wmma::load_matrix_sync(bHi, &Vh[(k16 * 16) * AT_LD + wc * 32 + et * 16], AT_LD);
                    wmma::load_matrix_sync(bLo, &Vl[(k16 * 16) * AT_LD + wc * 32 + et * 16], AT_LD);
#pragma unroll
                    for (int i = 0; i < 2; i++)
                        MMA3(c[i][et], pHi[i], pLo[i], bHi, bLo);
                }
            }
#pragma unroll
            for (int i = 0; i < 2; i++)
#pragma unroll
                for (int et = 0; et < 2; et++)
                    wmma::store_matrix_sync(
                        &Os[(wr * 32 + i * 16) * SF_LD + wc * 32 + et * 16],
                        c[i][et], SF_LD, wmma::mem_row_major);
        }
        __syncthreads();   // (4) every read of Kh/Kl/Vh/Vl/Ph/Pl retired

        // ---- land the prefetched K/V tile (convert) and make it visible ----
        if (has_next) {
#pragma unroll
            for (int l = 0; l < 4; l++) {
                int idx = l * 256 + tid;
                int row = idx >> 4;
                int kc  = (idx & 15) * 4;
                uint2 hh, ll;
                split4(kp[l], hh, ll);
                *(uint2*)&Kh[row * AT_LD + kc] = hh;
                *(uint2*)&Kl[row * AT_LD + kc] = ll;
                split4(vp[l], hh, ll);
                *(uint2*)&Vh[row * AT_LD + kc] = hh;
                *(uint2*)&Vl[row * AT_LD + kc] = ll;
            }
            __syncthreads();   // (1) new K/V visible for next S phase
        }
    }

    // ---- epilogue: normalize rows, write ctx [b][s][h*DH+e] (2/row) ----
    {
        float inv = 1.0f / lden;
        const float* orow = &Os[srow_id * SF_LD + shalf * 32];
        float* dst = g_ctx + ((long)b * S_ + qb * 128 + srow_id) * D_
                   + h * DH_ + shalf * 32;
#pragma unroll
        for (int c4 = 0; c4 < 8; c4++) {
            float4 o = *(const float4*)&orow[c4 * 4];
            o.x *= inv; o.y *= inv; o.z *= inv; o.w *= inv;
            *(float4*)&dst[c4 * 4] = o;
        }
    }
}

// ---------------------------------------------------------------------------
// Kernel 3: output projection  out = ctx @ Wo + bo  (3xBF16 wmma).
// grid = (M/128, D/128), block = 256, 2 CTAs/SM. Same scheme as kernel 1.
// ---------------------------------------------------------------------------
__global__ __launch_bounds__(256, 2) void oproj_kernel(
    const float* __restrict__ Wo, const float* __restrict__ bo,
    float* __restrict__ out)
{
    extern __shared__ float smp[];
    bf16* Ah = (bf16*)smp;
    bf16* Al = Ah + A2;
    bf16* Bh = Al + A2;
    bf16* Bl = Bh + B2;
    float* Cs = smp;

    const int m0 = blockIdx.x * 128;
    const int n0 = blockIdx.y * 128;

    const int tid = threadIdx.x;
    const int w   = tid >> 5;
    const int wr  = w >> 1;
    const int wc  = w & 1;

    FragC acc[2][4];
#pragma unroll
    for (int i = 0; i < 2; i++)
#pragma unroll
        for (int j = 0; j < 4; j++) wmma::fill_fragment(acc[i][j], 0.0f);

    for (int k0 = 0; k0 < D_; k0 += 32) {
#pragma unroll
        for (int l = 0; l < 4; l++) {
            int idx = l * 256 + tid;
            int row = idx >> 3;
            int kc  = (idx & 7) * 4;
            float4 a = *(const float4*)(g_ctx + (long)(m0 + row) * D_ + k0 + kc);
            uint2 h, lo;
            split4(a, h, lo);
            *(uint2*)&Ah[row * AS_LD + kc] = h;
            *(uint2*)&Al[row * AS_LD + kc] = lo;
        }
#pragma unroll
        for (int l = 0; l < 4; l++) {
            int idx = l * 256 + tid;
            int kr  = idx >> 5;
            int n4  = (idx & 31) * 4;
            float4 b = *(const float4*)(Wo + (long)(k0 + kr) * D_ + n0 + n4);
            uint2 h, lo;
            split4(b, h, lo);
            *(uint2*)&Bh[kr * BS_LD + n4] = h;
            *(uint2*)&Bl[kr * BS_LD + n4] = lo;
        }
        __syncthreads();

#pragma unroll
        for (int k16 = 0; k16 < 2; k16++) {
            FragA aHi[2], aLo[2];
#pragma unroll
            for (int i = 0; i < 2; i++) {
                wmma::load_matrix_sync(aHi[i], &Ah[(wr * 32 + i * 16) * AS_LD + k16 * 16], AS_LD);
                wmma::load_matrix_sync(aLo[i], &Al[(wr * 32 + i * 16) * AS_LD + k16 * 16], AS_LD);
            }
#pragma unroll
            for (int j = 0; j < 4; j++) {
                FragB bHi, bLo;
                wmma::load_matrix_sync(bHi, &Bh[(k16 * 16) * BS_LD + wc * 64 + j * 16], BS_LD);
                wmma::load_matrix_sync(bLo, &Bl[(k16 * 16) * BS_LD + wc * 64 + j * 16], BS_LD);
#pragma unroll
                for (int i = 0; i < 2; i++)
                    MMA3(acc[i][j], aHi[i], aLo[i], bHi, bLo);
            }
        }
        __syncthreads();
    }

#pragma unroll
    for (int i = 0; i < 2; i++)
#pragma unroll
        for (int j = 0; j < 4; j++)
            wmma::store_matrix_sync(&Cs[(wr * 32 + i * 16) * CS_LD + wc * 64 + j * 16],
                                    acc[i][j], CS_LD, wmma::mem_row_major);
    __syncthreads();

    const int tx = tid & 15;
    const int ty = tid >> 4;

    float bia[8];
    *(float4*)&bia[0] = *(const float4*)(bo + n0 + tx * 8);
    *(float4*)&bia[4] = *(const float4*)(bo + n0 + tx * 8 + 4);

#pragma unroll
    for (int r = 0; r < 8; r++) {
        int mrow = m0 + ty * 8 + r;
        const float* src = &Cs[(ty * 8 + r) * CS_LD + tx * 8];
        float* dst = out + (long)mrow * D_ + n0 + tx * 8;
        float4 v0 = *(const float4*)src;
        float4 v1 = *(const float4*)(src + 4);
        v0.x += bia[0]; v0.y += bia[1]; v0.z += bia[2]; v0.w += bia[3];
        v1.x += bia[4]; v1.y += bia[5]; v1.z += bia[6]; v1.w += bia[7];
        *(float4*)dst       = v0;
        *(float4*)(dst + 4) = v1;
    }
}

// ---------------------------------------------------------------------------
// Entry point. Inputs per metadata order:
// x, Wq, Wk, Wv, bq, bk, bv, Wo, bo  (all float32). Output: [B,S,D] float32.
// Graph-capturable: kernel launches only. cudaFuncSetAttribute is a non-stream
// API (executes immediately, idempotent) — not an allocation.
// ---------------------------------------------------------------------------
extern "C" void kernel_launch(void* const* d_in, const int* in_sizes, int n_in,
                              void* d_out, int out_size)
{
    (void)in_sizes; (void)n_in; (void)out_size;

    const float* x  = (const float*)d_in[0];
    const float* Wq = (const float*)d_in[1];
    const float* Wk = (const float*)d_in[2];
    const float* Wv = (const float*)d_in[3];
    const float* bq = (const float*)d_in[4];
    const float* bk = (const float*)d_in[5];
    const float* bv = (const float*)d_in[6];
    const float* Wo = (const float*)d_in[7];
    const float* bo = (const float*)d_in[8];
    float* out = (float*)d_out;

    const int GEMM_SMEM = 128 * CS_LD * 4;   // 67584 B (fp32 epilogue alias dominates)
    const int ATTN_SMEM = (2 * 128 * SF_LD) * 4                       // Sf + Os
                        + (2 * 128 + 2 * 64 + 2 * 64 + 2 * 128) * AT_LD * 2;  // bf16 tiles
    // = 69632 + 110592 = 180224 B

    cudaFuncSetAttribute(qkv_kernel,
                         cudaFuncAttributeMaxDynamicSharedMemorySize, GEMM_SMEM);
    cudaFuncSetAttribute(attn_kernel,
                         cudaFuncAttributeMaxDynamicSharedMemorySize, ATTN_SMEM);
    cudaFuncSetAttribute(oproj_kernel,
                         cudaFuncAttributeMaxDynamicSharedMemorySize, GEMM_SMEM);

    qkv_kernel<<<dim3(M_ / 128, H_ / 2, 3), 256, GEMM_SMEM>>>(x, Wq, Wk, Wv, bq, bk, bv);
    attn_kernel<<<dim3(S_ / 128, H_, B_), 256, ATTN_SMEM>>>();
    oproj_kernel<<<dim3(M_ / 128, D_ / 128), 256, GEMM_SMEM>>>(Wo, bo, out);
}

// round 15
// speedup vs baseline: 2.5361x; 1.0252x over previous
#include <cuda_runtime.h>
#include <cuda_bf16.h>
#include <mma.h>

using namespace nvcuda;

// Problem constants (fixed by the reference)
#define B_  2
#define S_  2048
#define D_  1024
#define H_  16
#define DH_ 64
#define M_  (B_ * S_)   // 4096

typedef __nv_bfloat16 bf16;

// Scratch (allocation-free rule: __device__ globals)
__device__ float g_q[B_ * H_ * S_ * DH_];   // [b][h][s][dh]
__device__ float g_k[B_ * H_ * S_ * DH_];
__device__ float g_v[B_ * H_ * S_ * DH_];
__device__ float g_ctx[B_ * S_ * D_];       // [b][s][h*DH+e]

// Split one float4 into bf16 hi + bf16 lo quads (packed 8B each).
// hi = bf16(v); lo = bf16(v - hi). v - hi is exact in fp32.
__device__ __forceinline__ void split4(const float4 v, uint2& h, uint2& l) {
    bf16 hh[4], ll[4];
    float vv[4] = {v.x, v.y, v.z, v.w};
#pragma unroll
    for (int i = 0; i < 4; i++) {
        hh[i] = __float2bfloat16(vv[i]);
        ll[i] = __float2bfloat16(vv[i] - __bfloat162float(hh[i]));
    }
    h = *(uint2*)hh;
    l = *(uint2*)ll;
}

// acc += a * b with both operands hi/lo split (3 products; lo*lo dropped)
#define MMA3(acc, aHi, aLo, bHi, bLo)            \
    do {                                         \
        wmma::mma_sync(acc, aHi, bHi, acc);      \
        wmma::mma_sync(acc, aHi, bLo, acc);      \
        wmma::mma_sync(acc, aLo, bHi, acc);      \
    } while (0)

// SMEM strides
#define AS_LD 40    // GEMM A tile [128][40] bf16
#define BS_LD 136   // GEMM B tile [32][136] bf16
#define CS_LD 132   // GEMM fp32 epilogue tile [128][132]
#define AT_LD 72    // attention bf16 Q/K/V tiles (64 data + 8 pad halves)
#define SF_LD 68    // attention fp32 S/O tiles (64 data + 4 pad floats)
#define P_LD  136   // P (bf16) ldm in halves = SF_LD*2 (P aliases Sf rows)

#define A2 (128 * AS_LD)   // halves per GEMM A matrix
#define B2 (32 * BS_LD)    // halves per GEMM B matrix

typedef wmma::fragment<wmma::matrix_a, 16, 16, 16, bf16, wmma::row_major> FragA;
typedef wmma::fragment<wmma::matrix_b, 16, 16, 16, bf16, wmma::row_major> FragB;
typedef wmma::fragment<wmma::matrix_b, 16, 16, 16, bf16, wmma::col_major> FragBT;
typedef wmma::fragment<wmma::accumulator, 16, 16, 16, float> FragC;

// ---------------------------------------------------------------------------
// Kernel 1: fused per-head QKV projection (3xBF16 wmma) — UNCHANGED from the
// measured 308us version. grid=(M/128, H/2, 3), block=256, 2 CTAs/SM.
// ---------------------------------------------------------------------------
__global__ __launch_bounds__(256, 2) void qkv_kernel(
    const float* __restrict__ x,
    const float* __restrict__ Wq, const float* __restrict__ Wk,
    const float* __restrict__ Wv,
    const float* __restrict__ bq, const float* __restrict__ bk,
    const float* __restrict__ bv)
{
    extern __shared__ float smp[];
    bf16* Ah = (bf16*)smp;          // [128][AS_LD]
    bf16* Al = Ah + A2;
    bf16* Bh = Al + A2;             // [32][BS_LD]
    bf16* Bl = Bh + B2;
    float* Cs = smp;                // fp32 alias, used after final sync

    const int h0  = blockIdx.y * 2;
    const int m0  = blockIdx.x * 128;
    const int sel = blockIdx.z;

    const float* W    = (sel == 0) ? Wq : (sel == 1) ? Wk : Wv;
    const float* bias = (sel == 0) ? bq : (sel == 1) ? bk : bv;
    float*       out  = (sel == 0) ? g_q : (sel == 1) ? g_k : g_v;

    const int tid = threadIdx.x;
    const int w   = tid >> 5;
    const int wr  = w >> 1;
    const int wc  = w & 1;

    FragC acc[2][4];
#pragma unroll
    for (int i = 0; i < 2; i++)
#pragma unroll
        for (int j = 0; j < 4; j++) wmma::fill_fragment(acc[i][j], 0.0f);

    for (int k0 = 0; k0 < D_; k0 += 32) {
#pragma unroll
        for (int l = 0; l < 4; l++) {
            int idx = l * 256 + tid;
            int row = idx >> 3;
            int kc  = (idx & 7) * 4;
            float4 a = *(const float4*)(x + (long)(m0 + row) * D_ + k0 + kc);
            uint2 h, lo;
            split4(a, h, lo);
            *(uint2*)&Ah[row * AS_LD + kc] = h;
            *(uint2*)&Al[row * AS_LD + kc] = lo;
        }
#pragma unroll
        for (int l = 0; l < 4; l++) {
            int idx = l * 256 + tid;
            int kr  = idx >> 5;
            int n4  = (idx & 31) * 4;
            int hoff = n4 >> 6;
            int col  = n4 & 63;
            float4 b = *(const float4*)(W + (long)(h0 + hoff) * D_ * DH_
                                          + (long)(k0 + kr) * DH_ + col);
            uint2 h, lo;
            split4(b, h, lo);
            *(uint2*)&Bh[kr * BS_LD + n4] = h;
            *(uint2*)&Bl[kr * BS_LD + n4] = lo;
        }
        __syncthreads();

#pragma unroll
        for (int k16 = 0; k16 < 2; k16++) {
            FragA aHi[2], aLo[2];
#pragma unroll
            for (int i = 0; i < 2; i++) {
                wmma::load_matrix_sync(aHi[i], &Ah[(wr * 32 + i * 16) * AS_LD + k16 * 16], AS_LD);
                wmma::load_matrix_sync(aLo[i], &Al[(wr * 32 + i * 16) * AS_LD + k16 * 16], AS_LD);
            }
#pragma unroll
            for (int j = 0; j < 4; j++) {
                FragB bHi, bLo;
                wmma::load_matrix_sync(bHi, &Bh[(k16 * 16) * BS_LD + wc * 64 + j * 16], BS_LD);
                wmma::load_matrix_sync(bLo, &Bl[(k16 * 16) * BS_LD + wc * 64 + j * 16], BS_LD);
#pragma unroll
                for (int i = 0; i < 2; i++)
                    MMA3(acc[i][j], aHi[i], aLo[i], bHi, bLo);
            }
        }
        __syncthreads();
    }

#pragma unroll
    for (int i = 0; i < 2; i++)
#pragma unroll
        for (int j = 0; j < 4; j++)
            wmma::store_matrix_sync(&Cs[(wr * 32 + i * 16) * CS_LD + wc * 64 + j * 16],
                                    acc[i][j], CS_LD, wmma::mem_row_major);
    __syncthreads();

    const int tx = tid & 15;
    const int ty = tid >> 4;
    const int j0   = tx * 8;
    const int hoff = j0 >> 6;
    const int dh0  = j0 & 63;
    const int h    = h0 + hoff;

    float bia[8];
    *(float4*)&bia[0] = *(const float4*)(bias + h * DH_ + dh0);
    *(float4*)&bia[4] = *(const float4*)(bias + h * DH_ + dh0 + 4);

#pragma unroll
    for (int r = 0; r < 8; r++) {
        int m = m0 + ty * 8 + r;
        int b = m >> 11;
        int s = m & 2047;
        const float* src = &Cs[(ty * 8 + r) * CS_LD + tx * 8];
        float* dst = out + ((long)(b * H_ + h) * S_ + s) * DH_ + dh0;
        float4 v0 = *(const float4*)src;
        float4 v1 = *(const float4*)(src + 4);
        v0.x += bia[0]; v0.y += bia[1]; v0.z += bia[2]; v0.w += bia[3];
        v1.x += bia[4]; v1.y += bia[5]; v1.z += bia[6]; v1.w += bia[7];
        *(float4*)dst       = v0;
        *(float4*)(dst + 4) = v1;
    }
}

// ---------------------------------------------------------------------------
// Kernel 2: flash attention, 3xBF16 wmma, 2 CTAs/SM.
// grid = (S/64, H, B) = 1024 CTAs, block = 256 (8 warps).
// Tile: 64 q-rows x 64 k-cols per iteration.
// Warp w: rows (w>>1)*16 (1 tile), cols (w&1)*32 (2 tiles).
// Dynamic SMEM = 90112 B (fits 2 CTAs in 228 KB):
//   Sf [64][68] fp32 scores, ALIASED with P (bf16 hi/lo) per 64-B thread
//       windows: thread (row, qtr) reads S floats [qtr*16, +16) into regs,
//       then writes P hi (16 halves) + lo (16 halves) into exactly those
//       bytes — same-thread RAW only, no cross-thread hazard.
//   Os [64][68] fp32 O accumulator
//   Qh/Ql [64][72], Kh/Kl [64][72], Vh/Vl [64][72] bf16
// Softmax: FOUR threads per row (row = tid>>2, qtr = tid&3, 16 cols each);
// quad lanes are in-warp adjacent -> combine via shfl_xor 1 and 2.
// Barriers: 4 per iteration; cross-CTA overlap (2/SM) hides the stalls.
// ---------------------------------------------------------------------------
__global__ __launch_bounds__(256, 2) void attn_kernel()
{
    extern __shared__ float smp[];
    float* Sf = smp;                        // [64][68] fp32, P alias
    float* Os = Sf + 64 * SF_LD;            // [64][68] fp32
    bf16* Qh = (bf16*)(Os + 64 * SF_LD);    // [64][72]
    bf16* Ql = Qh + 64 * AT_LD;
    bf16* Kh = Ql + 64 * AT_LD;             // [64][72]
    bf16* Kl = Kh + 64 * AT_LD;
    bf16* Vh = Kl + 64 * AT_LD;             // [64][72]
    bf16* Vl = Vh + 64 * AT_LD;
    bf16* Pb = (bf16*)Sf;                   // P base (ldm = P_LD halves)

    const int qb = blockIdx.x;              // query block (64 rows)
    const int h  = blockIdx.y;
    const int b  = blockIdx.z;

    const long base = (long)(b * H_ + h) * S_ * DH_;
    const float* Q = g_q + base;
    const float* K = g_k + base;
    const float* V = g_v + base;

    const int tid = threadIdx.x;
    const int w   = tid >> 5;
    const int wr  = w >> 1;          // 0..3 -> rows wr*16
    const int wc  = w & 1;           // 0..1 -> cols wc*32

    const int srow = tid >> 2;       // softmax row (0..63)
    const int qtr  = tid & 3;        // 16-col quarter of the row

    // Q tile (scaled 1/8) -> bf16 hi/lo: 64x64 = 1024 float4, 4/thread
#pragma unroll
    for (int l = 0; l < 4; l++) {
        int idx = l * 256 + tid;
        int row = idx >> 4;
        int kc  = (idx & 15) * 4;
        float4 a = *(const float4*)(Q + (long)(qb * 64 + row) * DH_ + kc);
        a.x *= 0.125f; a.y *= 0.125f; a.z *= 0.125f; a.w *= 0.125f;
        uint2 hh, ll;
        split4(a, hh, ll);
        *(uint2*)&Qh[row * AT_LD + kc] = hh;
        *(uint2*)&Ql[row * AT_LD + kc] = ll;
    }
    // K/V tile 0
#pragma unroll
    for (int l = 0; l < 4; l++) {
        int idx = l * 256 + tid;
        int row = idx >> 4;
        int kc  = (idx & 15) * 4;
        uint2 hh, ll;
        split4(*(const float4*)(K + (long)row * DH_ + kc), hh, ll);
        *(uint2*)&Kh[row * AT_LD + kc] = hh;
        *(uint2*)&Kl[row * AT_LD + kc] = ll;
        split4(*(const float4*)(V + (long)row * DH_ + kc), hh, ll);
        *(uint2*)&Vh[row * AT_LD + kc] = hh;
        *(uint2*)&Vl[row * AT_LD + kc] = ll;
    }

    float mrow = -1e30f, lden = 0.0f;   // per-row state (quad-replicated)

    __syncthreads();   // Q/K/V visible

    for (int kb = 0; kb < S_; kb += 64) {
        const bool has_next = (kb + 64 < S_);

        // ---- S = Q @ K^T : warp region 16x32 (1x2 tiles), k16 outermost ----
        {
            FragC c[2];
            wmma::fill_fragment(c[0], 0.0f);
            wmma::fill_fragment(c[1], 0.0f);
#pragma unroll
            for (int k16 = 0; k16 < 4; k16++) {
                FragA aHi, aLo;
                wmma::load_matrix_sync(aHi, &Qh[(wr * 16) * AT_LD + k16 * 16], AT_LD);
                wmma::load_matrix_sync(aLo, &Ql[(wr * 16) * AT_LD + k16 * 16], AT_LD);
#pragma unroll
                for (int jt = 0; jt < 2; jt++) {
                    FragBT bHi, bLo;   // Kh[j][dh] viewed col-major: B[dh][j]
                    wmma::load_matrix_sync(bHi, &Kh[(wc * 32 + jt * 16) * AT_LD + k16 * 16], AT_LD);
                    wmma::load_matrix_sync(bLo, &Kl[(wc * 32 + jt * 16) * AT_LD + k16 * 16], AT_LD);
                    MMA3(c[jt], aHi, aLo, bHi, bLo);
                }
            }
#pragma unroll
            for (int jt = 0; jt < 2; jt++)
                wmma::store_matrix_sync(&Sf[(wr * 16) * SF_LD + wc * 32 + jt * 16],
                                        c[jt], SF_LD, wmma::mem_row_major);
        }
        __syncthreads();   // (2) S tile complete

        // ---- online softmax: 4 threads/row, 16 cols each, in-regs ----
        {
            const float* sp = &Sf[srow * SF_LD + qtr * 16];
            float4 s0 = *(const float4*)(sp + 0);
            float4 s1 = *(const float4*)(sp + 4);
            float4 s2 = *(const float4*)(sp + 8);
            float4 s3 = *(const float4*)(sp + 12);

            float mloc = fmaxf(fmaxf(fmaxf(s0.x, s0.y), fmaxf(s0.z, s0.w)),
                               fmaxf(fmaxf(s1.x, s1.y), fmaxf(s1.z, s1.w)));
            mloc = fmaxf(mloc, fmaxf(fmaxf(fmaxf(s2.x, s2.y), fmaxf(s2.z, s2.w)),
                                     fmaxf(fmaxf(s3.x, s3.y), fmaxf(s3.z, s3.w))));
            mloc = fmaxf(mloc, __shfl_xor_sync(0xffffffffu, mloc, 1));
            mloc = fmaxf(mloc, __shfl_xor_sync(0xffffffffu, mloc, 2));
            float mnew  = fmaxf(mrow, mloc);
            float alpha = __expf(mrow - mnew);
            mrow = mnew;

            float4 p[4];
            float rs = 0.0f;
            {
                float4 ss[4] = {s0, s1, s2, s3};
#pragma unroll
                for (int c4 = 0; c4 < 4; c4++) {
                    p[c4].x = __expf(ss[c4].x - mnew);
                    p[c4].y = __expf(ss[c4].y - mnew);
                    p[c4].z = __expf(ss[c4].z - mnew);
                    p[c4].w = __expf(ss[c4].w - mnew);
                    rs += (p[c4].x + p[c4].y) + (p[c4].z + p[c4].w);
                }
            }
            rs += __shfl_xor_sync(0xffffffffu, rs, 1);
            rs += __shfl_xor_sync(0xffffffffu, rs, 2);
            lden = lden * alpha + rs;

            // write P hi/lo into THIS thread's own S window (alias-safe)
            bf16* ph = Pb + srow * P_LD + qtr * 32;       // 16 halves hi
            bf16* pl = ph + 16;                           // 16 halves lo
#pragma unroll
            for (int c4 = 0; c4 < 4; c4++) {
                uint2 hh, ll;
                split4(p[c4], hh, ll);
                *(uint2*)&ph[c4 * 4] = hh;
                *(uint2*)&pl[c4 * 4] = ll;
            }

            float* orow = &Os[srow * SF_LD + qtr * 16];
            if (kb == 0) {
                float4 z = make_float4(0.f, 0.f, 0.f, 0.f);
#pragma unroll
                for (int c4 = 0; c4 < 4; c4++) *(float4*)&orow[c4 * 4] = z;
            } else {
#pragma unroll
                for (int c4 = 0; c4 < 4; c4++) {
                    float4 o = *(const float4*)&orow[c4 * 4];
                    o.x *= alpha; o.y *= alpha; o.z *= alpha; o.w *= alpha;
                    *(float4*)&orow[c4 * 4] = o;
                }
            }
        }
        __syncthreads();   // (3) P ready, O rescaled/zeroed

        // ---- O += P @ V : warp region rows wr*16, e-cols wc*32 ----
        {
            FragC c[2];
#pragma unroll
            for (int et = 0; et < 2; et++)
                wmma::load_matrix_sync(c[et],
                    &Os[(wr * 16) * SF_LD + wc * 32 + et * 16],
                    SF_LD, wmma::mem_row_major);

#pragma unroll
            for (int k16 = 0; k16 < 4; k16++) {
                // P k16-chunk: cols [k16*16, +16) at halves k16*32 (hi), +16 (lo)
                FragA pHi, pLo;
                wmma::load_matrix_sync(pHi, Pb + (wr * 16) * P_LD + k16 * 32, P_LD);
                wmma::load_matrix_sync(pLo, Pb + (wr * 16) * P_LD + k16 * 32 + 16, P_LD);
#pragma unroll
                for (int et = 0; et < 2; et++) {
                    FragB bHi, bLo;
                    wmma::load_matrix_sync(bHi, &Vh[(k16 * 16) * AT_LD + wc * 32 + et * 16], AT_LD);
                    wmma::load_matrix_sync(bLo, &Vl[(k16 * 16) * AT_LD + wc * 32 + et * 16], AT_LD);
                    MMA3(c[et], pHi, pLo, bHi, bLo);
                }
            }
#pragma unroll
            for (int et = 0; et < 2; et++)
                wmma::store_matrix_sync(
                    &Os[(wr * 16) * SF_LD + wc * 32 + et * 16],
                    c[et], SF_LD, wmma::mem_row_major);
        }
        __syncthreads();   // (4) all reads of Kh/Kl/Vh/Vl/P retired

        // ---- load next K/V tile ----
        if (has_next) {
#pragma unroll
            for (int l = 0; l < 4; l++) {
                int idx = l * 256 + tid;
                int row = idx >> 4;
                int kc  = (idx & 15) * 4;
                uint2 hh, ll;
                split4(*(const float4*)(K + (long)(kb + 64 + row) * DH_ + kc), hh, ll);
                *(uint2*)&Kh[row * AT_LD + kc] = hh;
                *(uint2*)&Kl[row * AT_LD + kc] = ll;
                split4(*(const float4*)(V + (long)(kb + 64 + row) * DH_ + kc), hh, ll);
                *(uint2*)&Vh[row * AT_LD + kc] = hh;
                *(uint2*)&Vl[row * AT_LD + kc] = ll;
            }
            __syncthreads();   // (1) new K/V visible
        }
    }

    // ---- epilogue: normalize rows, write ctx [b][s][h*DH+e] (4/row) ----
    {
        float inv = 1.0f / lden;
        const float* orow = &Os[srow * SF_LD + qtr * 16];
        float* dst = g_ctx + ((long)b * S_ + qb * 64 + srow) * D_
                   + h * DH_ + qtr * 16;
#pragma unroll
        for (int c4 = 0; c4 < 4; c4++) {
            float4 o = *(const float4*)&orow[c4 * 4];
            o.x *= inv; o.y *= inv; o.z *= inv; o.w *= inv;
            *(float4*)&dst[c4 * 4] = o;
        }
    }
}

// ---------------------------------------------------------------------------
// Kernel 3: output projection (3xBF16 wmma) — UNCHANGED from measured version.
// grid = (M/128, D/128), block = 256, 2 CTAs/SM.
// ---------------------------------------------------------------------------
__global__ __launch_bounds__(256, 2) void oproj_kernel(
    const float* __restrict__ Wo, const float* __restrict__ bo,
    float* __restrict__ out)
{
    extern __shared__ float smp[];
    bf16* Ah = (bf16*)smp;
    bf16* Al = Ah + A2;
    bf16* Bh = Al + A2;
    bf16* Bl = Bh + B2;
    float* Cs = smp;

    const int m0 = blockIdx.x * 128;
    const int n0 = blockIdx.y * 128;

    const int tid = threadIdx.x;
    const int w   = tid >> 5;
    const int wr  = w >> 1;
    const int wc  = w & 1;

    FragC acc[2][4];
#pragma unroll
    for (int i = 0; i < 2; i++)
#pragma unroll
        for (int j = 0; j < 4; j++) wmma::fill_fragment(acc[i][j], 0.0f);

    for (int k0 = 0; k0 < D_; k0 += 32) {
#pragma unroll
        for (int l = 0; l < 4; l++) {
            int idx = l * 256 + tid;
            int row = idx >> 3;
            int kc  = (idx & 7) * 4;
            float4 a = *(const float4*)(g_ctx + (long)(m0 + row) * D_ + k0 + kc);
            uint2 h, lo;
            split4(a, h, lo);
            *(uint2*)&Ah[row * AS_LD + kc] = h;
            *(uint2*)&Al[row * AS_LD + kc] = lo;
        }
#pragma unroll
        for (int l = 0; l < 4; l++) {
            int idx = l * 256 + tid;
            int kr  = idx >> 5;
            int n4  = (idx & 31) * 4;
            float4 b = *(const float4*)(Wo + (long)(k0 + kr) * D_ + n0 + n4);
            uint2 h, lo;
            split4(b, h, lo);
            *(uint2*)&Bh[kr * BS_LD + n4] = h;
            *(uint2*)&Bl[kr * BS_LD + n4] = lo;
        }
        __syncthreads();

#pragma unroll
        for (int k16 = 0; k16 < 2; k16++) {
            FragA aHi[2], aLo[2];
#pragma unroll
            for (int i = 0; i < 2; i++) {
                wmma::load_matrix_sync(aHi[i], &Ah[(wr * 32 + i * 16) * AS_LD + k16 * 16], AS_LD);
                wmma::load_matrix_sync(aLo[i], &Al[(wr * 32 + i * 16) * AS_LD + k16 * 16], AS_LD);
            }
#pragma unroll
            for (int j = 0; j < 4; j++) {
                FragB bHi, bLo;
                wmma::load_matrix_sync(bHi, &Bh[(k16 * 16) * BS_LD + wc * 64 + j * 16], BS_LD);
                wmma::load_matrix_sync(bLo, &Bl[(k16 * 16) * BS_LD + wc * 64 + j * 16], BS_LD);
#pragma unroll
                for (int i = 0; i < 2; i++)
                    MMA3(acc[i][j], aHi[i], aLo[i], bHi, bLo);
            }
        }
        __syncthreads();
    }

#pragma unroll
    for (int i = 0; i < 2; i++)
#pragma unroll
        for (int j = 0; j < 4; j++)
            wmma::store_matrix_sync(&Cs[(wr * 32 + i * 16) * CS_LD + wc * 64 + j * 16],
                                    acc[i][j], CS_LD, wmma::mem_row_major);
    __syncthreads();

    const int tx = tid & 15;
    const int ty = tid >> 4;

    float bia[8];
    *(float4*)&bia[0] = *(const float4*)(bo + n0 + tx * 8);
    *(float4*)&bia[4] = *(const float4*)(bo + n0 + tx * 8 + 4);

#pragma unroll
    for (int r = 0; r < 8; r++) {
        int mrow = m0 + ty * 8 + r;
        const float* src = &Cs[(ty * 8 + r) * CS_LD + tx * 8];
        float* dst = out + (long)mrow * D_ + n0 + tx * 8;
        float4 v0 = *(const float4*)src;
        float4 v1 = *(const float4*)(src + 4);
        v0.x += bia[0]; v0.y += bia[1]; v0.z += bia[2]; v0.w += bia[3];
        v1.x += bia[4]; v1.y += bia[5]; v1.z += bia[6]; v1.w += bia[7];
        *(float4*)dst       = v0;
        *(float4*)(dst + 4) = v1;
    }
}

// ---------------------------------------------------------------------------
// Entry point. Inputs per metadata order:
// x, Wq, Wk, Wv, bq, bk, bv, Wo, bo  (all float32). Output: [B,S,D] float32.
// Graph-capturable: kernel launches only.
// ---------------------------------------------------------------------------
extern "C" void kernel_launch(void* const* d_in, const int* in_sizes, int n_in,
                              void* d_out, int out_size)
{
    (void)in_sizes; (void)n_in; (void)out_size;

    const float* x  = (const float*)d_in[0];
    const float* Wq = (const float*)d_in[1];
    const float* Wk = (const float*)d_in[2];
    const float* Wv = (const float*)d_in[3];
    const float* bq = (const float*)d_in[4];
    const float* bk = (const float*)d_in[5];
    const float* bv = (const float*)d_in[6];
    const float* Wo = (const float*)d_in[7];
    const float* bo = (const float*)d_in[8];
    float* out = (float*)d_out;

    const int GEMM_SMEM = 128 * CS_LD * 4;   // 67584 B
    const int ATTN_SMEM = (2 * 64 * SF_LD) * 4          // Sf + Os (fp32)
                        + (6 * 64 * AT_LD) * 2;         // Qh/Ql/Kh/Kl/Vh/Vl
    // = 34816 + 55296 = 90112 B  -> 2 CTAs/SM

    cudaFuncSetAttribute(qkv_kernel,
                         cudaFuncAttributeMaxDynamicSharedMemorySize, GEMM_SMEM);
    cudaFuncSetAttribute(attn_kernel,
                         cudaFuncAttributeMaxDynamicSharedMemorySize, ATTN_SMEM);
    cudaFuncSetAttribute(oproj_kernel,
                         cudaFuncAttributeMaxDynamicSharedMemorySize, GEMM_SMEM);

    qkv_kernel<<<dim3(M_ / 128, H_ / 2, 3), 256, GEMM_SMEM>>>(x, Wq, Wk, Wv, bq, bk, bv);
    attn_kernel<<<dim3(S_ / 64, H_, B_), 256, ATTN_SMEM>>>();
    oproj_kernel<<<dim3(M_ / 128, D_ / 128), 256, GEMM_SMEM>>>(Wo, bo, out);
}